// round 7
// baseline (speedup 1.0000x reference)
#include <cuda_runtime.h>
#include <math.h>
#include <stdint.h>

// Problem constants
#define BATCH 4
#define TSZ   1024
#define DIM   1024
#define NHEAD 16
#define HDIM  64
#define C3    (3 * DIM)

// Scratch (allocation-free: __device__ globals)
__device__ float g_qkv[BATCH * TSZ * C3];   // [B,T,3C]
__device__ float g_att[BATCH * TSZ * DIM];  // [B,T,C]

// ---------------------------------------------------------------------------
// tf32 / mma / ldmatrix helpers
// ---------------------------------------------------------------------------
__device__ __forceinline__ uint32_t f2tf(float f) {
    uint32_t u;
    asm("cvt.rna.tf32.f32 %0, %1;" : "=r"(u) : "f"(f));
    return u;
}

__device__ __forceinline__ void mma_tf32(float c[4], const uint32_t a[4],
                                         uint32_t b0, uint32_t b1) {
    asm volatile(
        "mma.sync.aligned.m16n8k8.row.col.f32.tf32.tf32.f32 "
        "{%0,%1,%2,%3}, {%4,%5,%6,%7}, {%8,%9}, {%0,%1,%2,%3};"
        : "+f"(c[0]), "+f"(c[1]), "+f"(c[2]), "+f"(c[3])
        : "r"(a[0]), "r"(a[1]), "r"(a[2]), "r"(a[3]), "r"(b0), "r"(b1));
}

__device__ __forceinline__ void ldsm_x4(uint32_t& r0, uint32_t& r1, uint32_t& r2,
                                        uint32_t& r3, uint32_t saddr) {
    asm volatile(
        "ldmatrix.sync.aligned.m8n8.x4.shared.b16 {%0,%1,%2,%3}, [%4];"
        : "=r"(r0), "=r"(r1), "=r"(r2), "=r"(r3)
        : "r"(saddr));
}

// Fragment-lane address components:
#define A_ROW(lane) (((lane) & 7) + (((lane) >> 3) & 1) * 8)
#define A_KOF(lane) (((lane) >> 4) * 4)
#define B_ROW(lane) (((lane) & 7) + ((lane) >> 4) * 8)
#define B_KOF(lane) ((((lane) >> 3) & 1) * 4)

// ---------------------------------------------------------------------------
// TF32 GEMM (NT): C[m,n] = sum_k A[m,k]*B[n,k] (+bias[n])
// Block 128(M) x 256(N), BK=16, 512 threads = 16 warps (4x4), warp tile 32x64.
// Double-buffered dynamic smem; LDSM fragment loads; stride 20 (conflict-free).
// ---------------------------------------------------------------------------
#define BK 16
#define ASTR 20
#define SA_WORDS (128 * ASTR)
#define SB_WORDS (256 * ASTR)
#define GEMM_SMEM ((2 * (SA_WORDS + SB_WORDS)) * 4)

template <bool BIAS>
__global__ __launch_bounds__(512, 1)
void tf32_gemm_nt(const float* __restrict__ A, const float* __restrict__ B,
                  const float* __restrict__ bias, float* __restrict__ C,
                  int M, int N, int K) {
    extern __shared__ uint32_t gsm[];
    uint32_t* sAbuf[2] = {gsm, gsm + SA_WORDS + SB_WORDS};
    uint32_t* sBbuf[2] = {gsm + SA_WORDS, gsm + 2 * SA_WORDS + SB_WORDS};

    const int tid  = threadIdx.x;
    const int lane = tid & 31;
    const int warp = tid >> 5;         // 0..15
    const int g = lane >> 2;
    const int t = lane & 3;
    const int wm = (warp >> 2) * 32;   // 0,32,64,96
    const int wn = (warp & 3) * 64;    // 0,64,128,192
    const int bm = blockIdx.y * 128;
    const int bn = blockIdx.x * 256;

    const int lrow = tid >> 2;         // 0..127
    const int lcq  = (tid & 3) * 4;    // 0,4,8,12

    const float* Ap  = A + (size_t)(bm + lrow) * K + lcq;
    const float* Bp0 = B + (size_t)(bn + lrow) * K + lcq;
    const float* Bp1 = B + (size_t)(bn + 128 + lrow) * K + lcq;

    const uint32_t smem0 = (uint32_t)__cvta_generic_to_shared(gsm);
    const uint32_t sAoff[2] = {smem0, smem0 + 4u * (SA_WORDS + SB_WORDS)};
    const uint32_t sBoff[2] = {smem0 + 4u * SA_WORDS,
                               smem0 + 4u * (2 * SA_WORDS + SB_WORDS)};

    const int ar = A_ROW(lane), ak = A_KOF(lane);
    const int br = B_ROW(lane), bk = B_KOF(lane);

    float acc[2][8][4];
#pragma unroll
    for (int i = 0; i < 2; i++)
#pragma unroll
        for (int j = 0; j < 8; j++)
#pragma unroll
            for (int q = 0; q < 4; q++) acc[i][j][q] = 0.f;

    float4 ra, rb0, rb1;
    ra  = *(const float4*)(Ap);
    rb0 = *(const float4*)(Bp0);
    rb1 = *(const float4*)(Bp1);

    const int sbA  = lrow * ASTR + lcq;
    const int sbB1 = (128 + lrow) * ASTR + lcq;

#define STAGE(bufi)                                                            \
    do {                                                                       \
        uint4 u;                                                               \
        u.x = f2tf(ra.x); u.y = f2tf(ra.y); u.z = f2tf(ra.z); u.w = f2tf(ra.w);\
        *(uint4*)&sAbuf[bufi][sbA] = u;                                        \
        u.x = f2tf(rb0.x); u.y = f2tf(rb0.y); u.z = f2tf(rb0.z); u.w = f2tf(rb0.w); \
        *(uint4*)&sBbuf[bufi][sbA] = u;                                        \
        u.x = f2tf(rb1.x); u.y = f2tf(rb1.y); u.z = f2tf(rb1.z); u.w = f2tf(rb1.w); \
        *(uint4*)&sBbuf[bufi][sbB1] = u;                                       \
    } while (0)

    STAGE(0);
    __syncthreads();

    const int NT = K / BK;
    int buf = 0;
    for (int kt = 0; kt < NT; kt++) {
        if (kt + 1 < NT) {
            ra  = *(const float4*)(Ap + (kt + 1) * BK);
            rb0 = *(const float4*)(Bp0 + (kt + 1) * BK);
            rb1 = *(const float4*)(Bp1 + (kt + 1) * BK);
        }

        const uint32_t aA = sAoff[buf];
        const uint32_t aB = sBoff[buf];
#pragma unroll
        for (int kk = 0; kk < 2; kk++) {
            uint32_t af[2][4];
#pragma unroll
            for (int mt = 0; mt < 2; mt++)
                ldsm_x4(af[mt][0], af[mt][1], af[mt][2], af[mt][3],
                        aA + 4u * ((wm + mt * 16 + ar) * ASTR + kk * 8 + ak));
#pragma unroll
            for (int p = 0; p < 4; p++) {
                uint32_t b0, b1, b2, b3;
                ldsm_x4(b0, b1, b2, b3,
                        aB + 4u * ((wn + p * 16 + br) * ASTR + kk * 8 + bk));
#pragma unroll
                for (int mt = 0; mt < 2; mt++) {
                    mma_tf32(acc[mt][2 * p],     af[mt], b0, b1);
                    mma_tf32(acc[mt][2 * p + 1], af[mt], b2, b3);
                }
            }
        }

        if (kt + 1 < NT) {
            const int nb = buf ^ 1;
            STAGE(nb);
            __syncthreads();
            buf = nb;
        }
    }

    // Epilogue
#pragma unroll
    for (int mt = 0; mt < 2; mt++) {
#pragma unroll
        for (int nt = 0; nt < 8; nt++) {
            const float* a4 = acc[mt][nt];
            const int row = bm + wm + mt * 16 + g;
            const int col = bn + wn + nt * 8 + 2 * t;
            float bx = 0.f, by = 0.f;
            if (BIAS) { bx = bias[col]; by = bias[col + 1]; }
            float2 v0 = {a4[0] + bx, a4[1] + by};
            float2 v1 = {a4[2] + bx, a4[3] + by};
            *(float2*)(C + (size_t)row * N + col) = v0;
            *(float2*)(C + (size_t)(row + 8) * N + col) = v1;
        }
    }
}

// ---------------------------------------------------------------------------
// TF32 flash attention with LDSM fragment loads + K/V register prefetch.
// 256 threads = 8 warps, 128 q-rows, 16 kv-tiles of 64.
// ---------------------------------------------------------------------------
#define KSTR 68
#define VSTR 68
#define PSTR 68
#define FLASH_WORDS (64 * KSTR + 64 * VSTR + 128 * PSTR)
#define FLASH_SMEM  (FLASH_WORDS * 4)

__global__ __launch_bounds__(256)
void flash_tf32(const float* __restrict__ qkv, float* __restrict__ att) {
    extern __shared__ uint32_t fsm[];
    uint32_t* sK  = fsm;                         // [64][KSTR]
    uint32_t* sVT = fsm + 64 * KSTR;             // [64][VSTR]  d-major
    uint32_t* sQP = fsm + 64 * KSTR + 64 * VSTR; // [128][PSTR] Q then P

    const int tid  = threadIdx.x;
    const int lane = tid & 31;
    const int warp = tid >> 5;
    const int g = lane >> 2;
    const int t = lane & 3;
    const int bh = blockIdx.y;
    const int b = bh >> 4;
    const int h = bh & 15;
    const int q0 = blockIdx.x * 128;
    const size_t base = (size_t)b * TSZ * C3;
    const int hoff = h * HDIM;
    const float qscale = 0.125f * 1.44269504088896340736f;  // scale * log2(e)

    const uint32_t sKb  = (uint32_t)__cvta_generic_to_shared(sK);
    const uint32_t sVTb = (uint32_t)__cvta_generic_to_shared(sVT);
    const uint32_t sQPb = (uint32_t)__cvta_generic_to_shared(sQP);
    const uint32_t sPwb = sQPb + 4u * (warp * 16 * PSTR);

    const int ar = A_ROW(lane), ak = A_KOF(lane);
    const int br = B_ROW(lane), bk = B_KOF(lane);

    // Stage Q (128 x 64), pre-scaled, tf32-rounded
    for (int i = tid; i < 128 * 16; i += 256) {
        int r = i >> 4, c4 = (i & 15) * 4;
        float4 v = *(const float4*)(qkv + base + (size_t)(q0 + r) * C3 + hoff + c4);
        uint4 u;
        u.x = f2tf(v.x * qscale); u.y = f2tf(v.y * qscale);
        u.z = f2tf(v.z * qscale); u.w = f2tf(v.w * qscale);
        *(uint4*)&sQP[r * PSTR + c4] = u;
    }
    __syncthreads();

    // Q fragments via LDSM (warp-private 16 rows)
    uint32_t aq[8][4];
#pragma unroll
    for (int kk = 0; kk < 8; kk++)
        ldsm_x4(aq[kk][0], aq[kk][1], aq[kk][2], aq[kk][3],
                sQPb + 4u * ((warp * 16 + ar) * PSTR + kk * 8 + ak));

    float accO[8][4];
#pragma unroll
    for (int i = 0; i < 8; i++)
#pragma unroll
        for (int j = 0; j < 4; j++) accO[i][j] = 0.f;
    float m0 = -INFINITY, m1 = -INFINITY, l0 = 0.f, l1 = 0.f;

    // Staging map: lane->row (conflict-free transposed V store)
    const int sr  = (warp & 1) * 32 + lane;  // kv row 0..63
    const int scw = warp >> 1;               // chunk base 0..3

    // Prefetch tile 0 K/V into registers
    float4 pk[4], pv[4];
#pragma unroll
    for (int k = 0; k < 4; k++) {
        const int c4 = (scw + 4 * k) * 4;
        const float* src = qkv + base + (size_t)sr * C3 + hoff + c4;
        pk[k] = *(const float4*)(src + DIM);
        pv[k] = *(const float4*)(src + 2 * DIM);
    }

    for (int kt = 0; kt < 16; kt++) {
        __syncthreads();  // prior tile's sK/sVT readers done (Q frags in regs)
        // Store prefetched K/V (tf32-rounded)
#pragma unroll
        for (int k = 0; k < 4; k++) {
            const int c4 = (scw + 4 * k) * 4;
            uint4 uk;
            uk.x = f2tf(pk[k].x); uk.y = f2tf(pk[k].y);
            uk.z = f2tf(pk[k].z); uk.w = f2tf(pk[k].w);
            *(uint4*)&sK[sr * KSTR + c4] = uk;
            sVT[(c4 + 0) * VSTR + sr] = f2tf(pv[k].x);
            sVT[(c4 + 1) * VSTR + sr] = f2tf(pv[k].y);
            sVT[(c4 + 2) * VSTR + sr] = f2tf(pv[k].z);
            sVT[(c4 + 3) * VSTR + sr] = f2tf(pv[k].w);
        }
        __syncthreads();

        // Prefetch next tile (overlaps with compute below)
        if (kt < 15) {
#pragma unroll
            for (int k = 0; k < 4; k++) {
                const int c4 = (scw + 4 * k) * 4;
                const float* src =
                    qkv + base + (size_t)((kt + 1) * 64 + sr) * C3 + hoff + c4;
                pk[k] = *(const float4*)(src + DIM);
                pv[k] = *(const float4*)(src + 2 * DIM);
            }
        }

        // S = Qs * K^T (base-2 logits)
        float accS[8][4];
#pragma unroll
        for (int i = 0; i < 8; i++)
#pragma unroll
            for (int j = 0; j < 4; j++) accS[i][j] = 0.f;
#pragma unroll
        for (int kk = 0; kk < 8; kk++) {
#pragma unroll
            for (int p = 0; p < 4; p++) {
                uint32_t k0, k1, k2, k3;
                ldsm_x4(k0, k1, k2, k3,
                        sKb + 4u * ((p * 16 + br) * KSTR + kk * 8 + bk));
                mma_tf32(accS[2 * p],     aq[kk], k0, k1);
                mma_tf32(accS[2 * p + 1], aq[kk], k2, k3);
            }
        }

        // Online softmax (rows g, g+8), base-2 domain
        float r0 = -INFINITY, r1 = -INFINITY;
#pragma unroll
        for (int nt = 0; nt < 8; nt++) {
            r0 = fmaxf(r0, fmaxf(accS[nt][0], accS[nt][1]));
            r1 = fmaxf(r1, fmaxf(accS[nt][2], accS[nt][3]));
        }
        r0 = fmaxf(r0, __shfl_xor_sync(0xffffffffu, r0, 1));
        r0 = fmaxf(r0, __shfl_xor_sync(0xffffffffu, r0, 2));
        r1 = fmaxf(r1, __shfl_xor_sync(0xffffffffu, r1, 1));
        r1 = fmaxf(r1, __shfl_xor_sync(0xffffffffu, r1, 2));
        const float mn0 = fmaxf(m0, r0);
        const float mn1 = fmaxf(m1, r1);
        const float al0 = exp2f(m0 - mn0);
        const float al1 = exp2f(m1 - mn1);
        float rs0 = 0.f, rs1 = 0.f;
        uint32_t* sPw = sQP + warp * 16 * PSTR;
#pragma unroll
        for (int nt = 0; nt < 8; nt++) {
            uint32_t p0 = f2tf(exp2f(accS[nt][0] - mn0));
            uint32_t p1 = f2tf(exp2f(accS[nt][1] - mn0));
            uint32_t p2 = f2tf(exp2f(accS[nt][2] - mn1));
            uint32_t p3 = f2tf(exp2f(accS[nt][3] - mn1));
            rs0 += __uint_as_float(p0) + __uint_as_float(p1);
            rs1 += __uint_as_float(p2) + __uint_as_float(p3);
            uint2 w0 = {p0, p1}, w1 = {p2, p3};
            *(uint2*)&sPw[g * PSTR + nt * 8 + 2 * t] = w0;
            *(uint2*)&sPw[(g + 8) * PSTR + nt * 8 + 2 * t] = w1;
        }
        rs0 += __shfl_xor_sync(0xffffffffu, rs0, 1);
        rs0 += __shfl_xor_sync(0xffffffffu, rs0, 2);
        rs1 += __shfl_xor_sync(0xffffffffu, rs1, 1);
        rs1 += __shfl_xor_sync(0xffffffffu, rs1, 2);
        l0 = l0 * al0 + rs0;
        l1 = l1 * al1 + rs1;
        m0 = mn0; m1 = mn1;
#pragma unroll
        for (int nt = 0; nt < 8; nt++) {
            accO[nt][0] *= al0; accO[nt][1] *= al0;
            accO[nt][2] *= al1; accO[nt][3] *= al1;
        }
        __syncwarp();

        // O += P V  (P via A-frag LDSM, V via B-frag LDSM from sVT)
#pragma unroll
        for (int kk = 0; kk < 8; kk++) {
            uint32_t ap[4];
            ldsm_x4(ap[0], ap[1], ap[2], ap[3],
                    sPwb + 4u * (ar * PSTR + kk * 8 + ak));
#pragma unroll
            for (int p = 0; p < 4; p++) {
                uint32_t v0, v1, v2, v3;
                ldsm_x4(v0, v1, v2, v3,
                        sVTb + 4u * ((p * 16 + br) * VSTR + kk * 8 + bk));
                mma_tf32(accO[2 * p],     ap, v0, v1);
                mma_tf32(accO[2 * p + 1], ap, v2, v3);
            }
        }
    }

    // Epilogue: normalize, write [B,T,C]
    const float inv0 = 1.f / l0;
    const float inv1 = 1.f / l1;
    const int r0w = q0 + warp * 16 + g;
    float* o0 = att + (size_t)b * TSZ * DIM + (size_t)r0w * DIM + hoff;
    float* o1 = o0 + (size_t)8 * DIM;
#pragma unroll
    for (int nt = 0; nt < 8; nt++) {
        float2 v0 = {accO[nt][0] * inv0, accO[nt][1] * inv0};
        float2 v1 = {accO[nt][2] * inv1, accO[nt][3] * inv1};
        *(float2*)(o0 + nt * 8 + 2 * t) = v0;
        *(float2*)(o1 + nt * 8 + 2 * t) = v1;
    }
}

// ---------------------------------------------------------------------------
extern "C" void kernel_launch(void* const* d_in, const int* in_sizes, int n_in,
                              void* d_out, int out_size) {
    const float* x     = (const float*)d_in[0];  // [4,1024,1024]
    const float* Wqkv  = (const float*)d_in[1];  // [3072,1024]
    const float* Wproj = (const float*)d_in[2];  // [1024,1024]
    const float* bproj = (const float*)d_in[3];  // [1024]
    float* out = (float*)d_out;                  // [4,1024,1024]

    float *qkv, *att;
    cudaGetSymbolAddress((void**)&qkv, g_qkv);
    cudaGetSymbolAddress((void**)&att, g_att);

    cudaFuncSetAttribute(tf32_gemm_nt<false>,
                         cudaFuncAttributeMaxDynamicSharedMemorySize, GEMM_SMEM);
    cudaFuncSetAttribute(tf32_gemm_nt<true>,
                         cudaFuncAttributeMaxDynamicSharedMemorySize, GEMM_SMEM);
    cudaFuncSetAttribute(flash_tf32,
                         cudaFuncAttributeMaxDynamicSharedMemorySize, FLASH_SMEM);

    // 1) QKV projection: [4096,1024] x [3072,1024]^T -> [4096,3072]
    tf32_gemm_nt<false><<<dim3(C3 / 256, (BATCH * TSZ) / 128), 512, GEMM_SMEM>>>(
        x, Wqkv, nullptr, qkv, BATCH * TSZ, C3, DIM);

    // 2) Attention (tf32 mma flash, LDSM + prefetch)
    flash_tf32<<<dim3(TSZ / 128, BATCH * NHEAD), 256, FLASH_SMEM>>>(qkv, att);

    // 3) Output projection + bias: [4096,1024] x [1024,1024]^T -> [4096,1024]
    tf32_gemm_nt<true><<<dim3(DIM / 256, (BATCH * TSZ) / 128), 512, GEMM_SMEM>>>(
        att, Wproj, bproj, out, BATCH * TSZ, DIM, DIM);
}

// round 8
// speedup vs baseline: 1.8295x; 1.8295x over previous
#include <cuda_runtime.h>
#include <cuda_fp16.h>
#include <math.h>
#include <stdint.h>

// Problem constants
#define BATCH 4
#define TSZ   1024
#define DIM   1024
#define NHEAD 16
#define HDIM  64
#define C3    (3 * DIM)

// Scratch (allocation-free: __device__ globals)
__device__ float g_qkv[BATCH * TSZ * C3];   // [B,T,3C]
__device__ float g_att[BATCH * TSZ * DIM];  // [B,T,C]

// ---------------------------------------------------------------------------
// fp16 mma / ldmatrix helpers
// ---------------------------------------------------------------------------
__device__ __forceinline__ void mma_f16(float c[4], const uint32_t a[4],
                                        uint32_t b0, uint32_t b1) {
    asm volatile(
        "mma.sync.aligned.m16n8k16.row.col.f32.f16.f16.f32 "
        "{%0,%1,%2,%3}, {%4,%5,%6,%7}, {%8,%9}, {%0,%1,%2,%3};"
        : "+f"(c[0]), "+f"(c[1]), "+f"(c[2]), "+f"(c[3])
        : "r"(a[0]), "r"(a[1]), "r"(a[2]), "r"(a[3]), "r"(b0), "r"(b1));
}

__device__ __forceinline__ void ldsm_x4(uint32_t& r0, uint32_t& r1, uint32_t& r2,
                                        uint32_t& r3, uint32_t saddr) {
    asm volatile(
        "ldmatrix.sync.aligned.m8n8.x4.shared.b16 {%0,%1,%2,%3}, [%4];"
        : "=r"(r0), "=r"(r1), "=r"(r2), "=r"(r3)
        : "r"(saddr));
}

__device__ __forceinline__ void ldsm_x4_trans(uint32_t& r0, uint32_t& r1,
                                              uint32_t& r2, uint32_t& r3,
                                              uint32_t saddr) {
    asm volatile(
        "ldmatrix.sync.aligned.m8n8.x4.trans.shared.b16 {%0,%1,%2,%3}, [%4];"
        : "=r"(r0), "=r"(r1), "=r"(r2), "=r"(r3)
        : "r"(saddr));
}

// 8 floats -> 8 halves packed in uint4
__device__ __forceinline__ uint4 f8_to_h8(float4 a, float4 b) {
    __half2 h0 = __floats2half2_rn(a.x, a.y);
    __half2 h1 = __floats2half2_rn(a.z, a.w);
    __half2 h2 = __floats2half2_rn(b.x, b.y);
    __half2 h3 = __floats2half2_rn(b.z, b.w);
    uint4 u;
    u.x = *(uint32_t*)&h0; u.y = *(uint32_t*)&h1;
    u.z = *(uint32_t*)&h2; u.w = *(uint32_t*)&h3;
    return u;
}

// fp16 m16n8k16 fragment lane->address components (offsets in halves):
// A x4: matrices {r0-7/k0-7, r8-15/k0-7, r0-7/k8-15, r8-15/k8-15}
#define A16_ROW(lane) ((lane) & 15)
#define A16_KOF(lane) (((lane) >> 4) * 8)
// B x4 (non-trans): {n0-7/k0-7, n0-7/k8-15, n8-15/k0-7, n8-15/k8-15}
//   -> MMA(n0-7) uses {r0,r1}; MMA(n8-15) uses {r2,r3}
#define B16_ROW(lane) (((lane) & 7) + ((lane) >> 4) * 8)
#define B16_KOF(lane) ((((lane) >> 3) & 1) * 8)

// ---------------------------------------------------------------------------
// FP16 GEMM (NT): C[m,n] = sum_k A[m,k]*B[n,k] (+bias[n])
// Block 128(M) x 256(N), BK=32 halves, 512 threads = 16 warps (4x4),
// warp tile 32x64. Double-buffered smem, stride 40 halves (5 coprime 8 ->
// conflict-free ldmatrix).
// ---------------------------------------------------------------------------
#define BK 32
#define ASTR 40
#define SA_H (128 * ASTR)
#define SB_H (256 * ASTR)
#define GEMM_SMEM ((2 * (SA_H + SB_H)) * 2)

template <bool BIAS>
__global__ __launch_bounds__(512, 1)
void f16_gemm_nt(const float* __restrict__ A, const float* __restrict__ B,
                 const float* __restrict__ bias, float* __restrict__ C,
                 int M, int N, int K) {
    extern __shared__ __half gsm[];
    __half* sAbuf[2] = {gsm, gsm + SA_H + SB_H};
    __half* sBbuf[2] = {gsm + SA_H, gsm + 2 * SA_H + SB_H};

    const int tid  = threadIdx.x;
    const int lane = tid & 31;
    const int warp = tid >> 5;         // 0..15
    const int g = lane >> 2;
    const int t = lane & 3;
    const int wm = (warp >> 2) * 32;   // 0,32,64,96
    const int wn = (warp & 3) * 64;    // 0,64,128,192
    const int bm = blockIdx.y * 128;
    const int bn = blockIdx.x * 256;

    const int lrow = tid >> 2;         // 0..127
    const int lkq  = (tid & 3) * 8;    // half offset 0,8,16,24

    const float* Ap  = A + (size_t)(bm + lrow) * K + lkq;
    const float* Bp0 = B + (size_t)(bn + lrow) * K + lkq;
    const float* Bp1 = B + (size_t)(bn + 128 + lrow) * K + lkq;

    const uint32_t smem0 = (uint32_t)__cvta_generic_to_shared(gsm);
    const uint32_t sAoff[2] = {smem0, smem0 + 2u * (SA_H + SB_H)};
    const uint32_t sBoff[2] = {smem0 + 2u * SA_H,
                               smem0 + 2u * (2 * SA_H + SB_H)};

    const int ar = A16_ROW(lane), ak = A16_KOF(lane);
    const int br = B16_ROW(lane), bk = B16_KOF(lane);

    float acc[2][8][4];
#pragma unroll
    for (int i = 0; i < 2; i++)
#pragma unroll
        for (int j = 0; j < 8; j++)
#pragma unroll
            for (int q = 0; q < 4; q++) acc[i][j][q] = 0.f;

    float4 ra0, ra1, rb00, rb01, rb10, rb11;
    ra0  = *(const float4*)(Ap);
    ra1  = *(const float4*)(Ap + 4);
    rb00 = *(const float4*)(Bp0);
    rb01 = *(const float4*)(Bp0 + 4);
    rb10 = *(const float4*)(Bp1);
    rb11 = *(const float4*)(Bp1 + 4);

    const int sbA  = lrow * ASTR + lkq;
    const int sbB1 = (128 + lrow) * ASTR + lkq;

#define STAGE(bufi)                                                            \
    do {                                                                       \
        *(uint4*)&sAbuf[bufi][sbA]  = f8_to_h8(ra0, ra1);                      \
        *(uint4*)&sBbuf[bufi][sbA]  = f8_to_h8(rb00, rb01);                    \
        *(uint4*)&sBbuf[bufi][sbB1] = f8_to_h8(rb10, rb11);                    \
    } while (0)

    STAGE(0);
    __syncthreads();

    const int NT = K / BK;
    int buf = 0;
    for (int kt = 0; kt < NT; kt++) {
        if (kt + 1 < NT) {
            ra0  = *(const float4*)(Ap + (kt + 1) * BK);
            ra1  = *(const float4*)(Ap + (kt + 1) * BK + 4);
            rb00 = *(const float4*)(Bp0 + (kt + 1) * BK);
            rb01 = *(const float4*)(Bp0 + (kt + 1) * BK + 4);
            rb10 = *(const float4*)(Bp1 + (kt + 1) * BK);
            rb11 = *(const float4*)(Bp1 + (kt + 1) * BK + 4);
        }

        const uint32_t aA = sAoff[buf];
        const uint32_t aB = sBoff[buf];
#pragma unroll
        for (int kk = 0; kk < 2; kk++) {   // two k16 per BK=32
            uint32_t af[2][4];
#pragma unroll
            for (int mt = 0; mt < 2; mt++)
                ldsm_x4(af[mt][0], af[mt][1], af[mt][2], af[mt][3],
                        aA + 2u * ((wm + mt * 16 + ar) * ASTR + kk * 16 + ak));
#pragma unroll
            for (int p = 0; p < 4; p++) {
                uint32_t b0, b1, b2, b3;
                ldsm_x4(b0, b1, b2, b3,
                        aB + 2u * ((wn + p * 16 + br) * ASTR + kk * 16 + bk));
#pragma unroll
                for (int mt = 0; mt < 2; mt++) {
                    mma_f16(acc[mt][2 * p],     af[mt], b0, b1);
                    mma_f16(acc[mt][2 * p + 1], af[mt], b2, b3);
                }
            }
        }

        if (kt + 1 < NT) {
            const int nb = buf ^ 1;
            STAGE(nb);
            __syncthreads();
            buf = nb;
        }
    }

    // Epilogue (fp32 C fragments: rows g/g+8, cols 2t,2t+1)
#pragma unroll
    for (int mt = 0; mt < 2; mt++) {
#pragma unroll
        for (int nt = 0; nt < 8; nt++) {
            const float* a4 = acc[mt][nt];
            const int row = bm + wm + mt * 16 + g;
            const int col = bn + wn + nt * 8 + 2 * t;
            float bx = 0.f, by = 0.f;
            if (BIAS) { bx = bias[col]; by = bias[col + 1]; }
            float2 v0 = {a4[0] + bx, a4[1] + by};
            float2 v1 = {a4[2] + bx, a4[3] + by};
            *(float2*)(C + (size_t)row * N + col) = v0;
            *(float2*)(C + (size_t)(row + 8) * N + col) = v1;
        }
    }
}

// ---------------------------------------------------------------------------
// FP16 flash attention.
// 256 threads = 8 warps, 128 q-rows, 16 kv-tiles of 64.
// sK[j][d], sV[j][d] row-major stride 72 halves (9 coprime 8 -> conflict-free).
// V B-fragments via ldmatrix.trans (no transposed stores).
// sQP: Q staging then warp-private P slices, stride 72.
// ---------------------------------------------------------------------------
#define FSTR 72
#define FLASH_HALVES (FSTR * (64 + 64 + 128))
#define FLASH_SMEM   (FLASH_HALVES * 2)

__global__ __launch_bounds__(256)
void flash_f16(const float* __restrict__ qkv, float* __restrict__ att) {
    extern __shared__ __half fsm[];
    __half* sK  = fsm;                       // [64][FSTR]
    __half* sV  = fsm + 64 * FSTR;           // [64][FSTR]
    __half* sQP = fsm + 128 * FSTR;          // [128][FSTR] Q then P slices

    const int tid  = threadIdx.x;
    const int lane = tid & 31;
    const int warp = tid >> 5;
    const int g = lane >> 2;
    const int t = lane & 3;
    const int bh = blockIdx.y;
    const int b = bh >> 4;
    const int h = bh & 15;
    const int q0 = blockIdx.x * 128;
    const size_t base = (size_t)b * TSZ * C3;
    const int hoff = h * HDIM;
    const float qscale = 0.125f * 1.44269504088896340736f;  // scale * log2(e)

    const uint32_t sKb  = (uint32_t)__cvta_generic_to_shared(sK);
    const uint32_t sVb  = (uint32_t)__cvta_generic_to_shared(sV);
    const uint32_t sQPb = (uint32_t)__cvta_generic_to_shared(sQP);
    const uint32_t sPwb = sQPb + 2u * (warp * 16 * FSTR);

    const int ar = A16_ROW(lane), ak = A16_KOF(lane);
    const int br = B16_ROW(lane), bk = B16_KOF(lane);
    // V trans-ldsm lane addressing: k-row = j, n-col = d
    const int vj = (lane & 7) + ((lane >> 3) & 1) * 8;
    const int vd = (lane >> 4) * 8;

    // Stage Q (128 x 64), pre-scaled, fp16
    for (int i = tid; i < 128 * 8; i += 256) {
        int r = i >> 3, c8 = (i & 7) * 8;
        const float* src = qkv + base + (size_t)(q0 + r) * C3 + hoff + c8;
        float4 v0 = *(const float4*)(src);
        float4 v1 = *(const float4*)(src + 4);
        v0.x *= qscale; v0.y *= qscale; v0.z *= qscale; v0.w *= qscale;
        v1.x *= qscale; v1.y *= qscale; v1.z *= qscale; v1.w *= qscale;
        *(uint4*)&sQP[r * FSTR + c8] = f8_to_h8(v0, v1);
    }
    __syncthreads();

    // Q fragments via LDSM (warp-private 16 rows), 4 k16-groups over d=64
    uint32_t aq[4][4];
#pragma unroll
    for (int kk = 0; kk < 4; kk++)
        ldsm_x4(aq[kk][0], aq[kk][1], aq[kk][2], aq[kk][3],
                sQPb + 2u * ((warp * 16 + ar) * FSTR + kk * 16 + ak));

    float accO[8][4];
#pragma unroll
    for (int i = 0; i < 8; i++)
#pragma unroll
        for (int j = 0; j < 4; j++) accO[i][j] = 0.f;
    float m0 = -INFINITY, m1 = -INFINITY, l0 = 0.f, l1 = 0.f;

    // K/V staging map: row = tid>>2 (0..63), 16-half chunk = (tid&3)*16
    const int sr = tid >> 2;
    const int sc = (tid & 3) * 16;

    for (int kt = 0; kt < 16; kt++) {
        __syncthreads();  // prior tile's sK/sV readers done (Q frags in regs)
        {
            const float* src = qkv + base + (size_t)(kt * 64 + sr) * C3 + hoff + sc;
            float4 k0 = *(const float4*)(src + DIM);
            float4 k1 = *(const float4*)(src + DIM + 4);
            float4 k2 = *(const float4*)(src + DIM + 8);
            float4 k3 = *(const float4*)(src + DIM + 12);
            *(uint4*)&sK[sr * FSTR + sc]     = f8_to_h8(k0, k1);
            *(uint4*)&sK[sr * FSTR + sc + 8] = f8_to_h8(k2, k3);
            float4 w0 = *(const float4*)(src + 2 * DIM);
            float4 w1 = *(const float4*)(src + 2 * DIM + 4);
            float4 w2 = *(const float4*)(src + 2 * DIM + 8);
            float4 w3 = *(const float4*)(src + 2 * DIM + 12);
            *(uint4*)&sV[sr * FSTR + sc]     = f8_to_h8(w0, w1);
            *(uint4*)&sV[sr * FSTR + sc + 8] = f8_to_h8(w2, w3);
        }
        __syncthreads();

        // S = Qs * K^T (base-2 logits); accS[nt] covers kv cols nt*8..+7
        float accS[8][4];
#pragma unroll
        for (int i = 0; i < 8; i++)
#pragma unroll
            for (int j = 0; j < 4; j++) accS[i][j] = 0.f;
#pragma unroll
        for (int kk = 0; kk < 4; kk++) {
#pragma unroll
            for (int p = 0; p < 4; p++) {
                uint32_t b0, b1, b2, b3;
                ldsm_x4(b0, b1, b2, b3,
                        sKb + 2u * ((p * 16 + br) * FSTR + kk * 16 + bk));
                mma_f16(accS[2 * p],     aq[kk], b0, b1);
                mma_f16(accS[2 * p + 1], aq[kk], b2, b3);
            }
        }

        // Online softmax (rows g, g+8), base-2 domain
        float r0 = -INFINITY, r1 = -INFINITY;
#pragma unroll
        for (int nt = 0; nt < 8; nt++) {
            r0 = fmaxf(r0, fmaxf(accS[nt][0], accS[nt][1]));
            r1 = fmaxf(r1, fmaxf(accS[nt][2], accS[nt][3]));
        }
        r0 = fmaxf(r0, __shfl_xor_sync(0xffffffffu, r0, 1));
        r0 = fmaxf(r0, __shfl_xor_sync(0xffffffffu, r0, 2));
        r1 = fmaxf(r1, __shfl_xor_sync(0xffffffffu, r1, 1));
        r1 = fmaxf(r1, __shfl_xor_sync(0xffffffffu, r1, 2));
        const float mn0 = fmaxf(m0, r0);
        const float mn1 = fmaxf(m1, r1);
        const float al0 = exp2f(m0 - mn0);
        const float al1 = exp2f(m1 - mn1);
        float rs0 = 0.f, rs1 = 0.f;
        __half* sPw = sQP + warp * 16 * FSTR;
#pragma unroll
        for (int nt = 0; nt < 8; nt++) {
            __half2 h01 = __floats2half2_rn(exp2f(accS[nt][0] - mn0),
                                            exp2f(accS[nt][1] - mn0));
            __half2 h23 = __floats2half2_rn(exp2f(accS[nt][2] - mn1),
                                            exp2f(accS[nt][3] - mn1));
            float2 f01 = __half22float2(h01);
            float2 f23 = __half22float2(h23);
            rs0 += f01.x + f01.y;
            rs1 += f23.x + f23.y;
            *(uint32_t*)&sPw[g * FSTR + nt * 8 + 2 * t]       = *(uint32_t*)&h01;
            *(uint32_t*)&sPw[(g + 8) * FSTR + nt * 8 + 2 * t] = *(uint32_t*)&h23;
        }
        rs0 += __shfl_xor_sync(0xffffffffu, rs0, 1);
        rs0 += __shfl_xor_sync(0xffffffffu, rs0, 2);
        rs1 += __shfl_xor_sync(0xffffffffu, rs1, 1);
        rs1 += __shfl_xor_sync(0xffffffffu, rs1, 2);
        l0 = l0 * al0 + rs0;
        l1 = l1 * al1 + rs1;
        m0 = mn0; m1 = mn1;
#pragma unroll
        for (int nt = 0; nt < 8; nt++) {
            accO[nt][0] *= al0; accO[nt][1] *= al0;
            accO[nt][2] *= al1; accO[nt][3] *= al1;
        }
        __syncwarp();

        // O += P V  (P: A-frag non-trans; V: B-frag via ldmatrix.trans)
#pragma unroll
        for (int kk = 0; kk < 4; kk++) {
            uint32_t ap[4];
            ldsm_x4(ap[0], ap[1], ap[2], ap[3],
                    sPwb + 2u * (ar * FSTR + kk * 16 + ak));
#pragma unroll
            for (int p = 0; p < 4; p++) {
                uint32_t v0, v1, v2, v3;
                ldsm_x4_trans(v0, v1, v2, v3,
                              sVb + 2u * ((kk * 16 + vj) * FSTR + p * 16 + vd));
                mma_f16(accO[2 * p],     ap, v0, v1);
                mma_f16(accO[2 * p + 1], ap, v2, v3);
            }
        }
    }

    // Epilogue: normalize, write [B,T,C]
    const float inv0 = 1.f / l0;
    const float inv1 = 1.f / l1;
    const int r0w = q0 + warp * 16 + g;
    float* o0 = att + (size_t)b * TSZ * DIM + (size_t)r0w * DIM + hoff;
    float* o1 = o0 + (size_t)8 * DIM;
#pragma unroll
    for (int nt = 0; nt < 8; nt++) {
        float2 v0 = {accO[nt][0] * inv0, accO[nt][1] * inv0};
        float2 v1 = {accO[nt][2] * inv1, accO[nt][3] * inv1};
        *(float2*)(o0 + nt * 8 + 2 * t) = v0;
        *(float2*)(o1 + nt * 8 + 2 * t) = v1;
    }
}

// ---------------------------------------------------------------------------
extern "C" void kernel_launch(void* const* d_in, const int* in_sizes, int n_in,
                              void* d_out, int out_size) {
    const float* x     = (const float*)d_in[0];  // [4,1024,1024]
    const float* Wqkv  = (const float*)d_in[1];  // [3072,1024]
    const float* Wproj = (const float*)d_in[2];  // [1024,1024]
    const float* bproj = (const float*)d_in[3];  // [1024]
    float* out = (float*)d_out;                  // [4,1024,1024]

    float *qkv, *att;
    cudaGetSymbolAddress((void**)&qkv, g_qkv);
    cudaGetSymbolAddress((void**)&att, g_att);

    cudaFuncSetAttribute(f16_gemm_nt<false>,
                         cudaFuncAttributeMaxDynamicSharedMemorySize, GEMM_SMEM);
    cudaFuncSetAttribute(f16_gemm_nt<true>,
                         cudaFuncAttributeMaxDynamicSharedMemorySize, GEMM_SMEM);
    cudaFuncSetAttribute(flash_f16,
                         cudaFuncAttributeMaxDynamicSharedMemorySize, FLASH_SMEM);

    // 1) QKV projection: [4096,1024] x [3072,1024]^T -> [4096,3072]
    f16_gemm_nt<false><<<dim3(C3 / 256, (BATCH * TSZ) / 128), 512, GEMM_SMEM>>>(
        x, Wqkv, nullptr, qkv, BATCH * TSZ, C3, DIM);

    // 2) Attention (fp16 mma flash)
    flash_f16<<<dim3(TSZ / 128, BATCH * NHEAD), 256, FLASH_SMEM>>>(qkv, att);

    // 3) Output projection + bias: [4096,1024] x [1024,1024]^T -> [4096,1024]
    f16_gemm_nt<true><<<dim3(DIM / 256, (BATCH * TSZ) / 128), 512, GEMM_SMEM>>>(
        att, Wproj, bproj, out, BATCH * TSZ, DIM, DIM);
}

// round 9
// speedup vs baseline: 2.2763x; 1.2443x over previous
#include <cuda_runtime.h>
#include <cuda_fp16.h>
#include <math.h>
#include <stdint.h>

// Problem constants
#define BATCH 4
#define TSZ   1024
#define DIM   1024
#define NHEAD 16
#define HDIM  64
#define C3    (3 * DIM)

// Scratch (allocation-free: __device__ globals) — fp16 pipeline
__device__ __half g_xh[BATCH * TSZ * DIM];
__device__ __half g_wqkvh[C3 * DIM];
__device__ __half g_wprojh[DIM * DIM];
__device__ __half g_qkvh[BATCH * TSZ * C3];   // [B,T,3C]
__device__ __half g_atth[BATCH * TSZ * DIM];  // [B,T,C]

// ---------------------------------------------------------------------------
// helpers
// ---------------------------------------------------------------------------
__device__ __forceinline__ void mma_f16(float c[4], const uint32_t a[4],
                                        uint32_t b0, uint32_t b1) {
    asm volatile(
        "mma.sync.aligned.m16n8k16.row.col.f32.f16.f16.f32 "
        "{%0,%1,%2,%3}, {%4,%5,%6,%7}, {%8,%9}, {%0,%1,%2,%3};"
        : "+f"(c[0]), "+f"(c[1]), "+f"(c[2]), "+f"(c[3])
        : "r"(a[0]), "r"(a[1]), "r"(a[2]), "r"(a[3]), "r"(b0), "r"(b1));
}

__device__ __forceinline__ void ldsm_x4(uint32_t& r0, uint32_t& r1, uint32_t& r2,
                                        uint32_t& r3, uint32_t saddr) {
    asm volatile(
        "ldmatrix.sync.aligned.m8n8.x4.shared.b16 {%0,%1,%2,%3}, [%4];"
        : "=r"(r0), "=r"(r1), "=r"(r2), "=r"(r3)
        : "r"(saddr));
}

__device__ __forceinline__ void ldsm_x4_trans(uint32_t& r0, uint32_t& r1,
                                              uint32_t& r2, uint32_t& r3,
                                              uint32_t saddr) {
    asm volatile(
        "ldmatrix.sync.aligned.m8n8.x4.trans.shared.b16 {%0,%1,%2,%3}, [%4];"
        : "=r"(r0), "=r"(r1), "=r"(r2), "=r"(r3)
        : "r"(saddr));
}

__device__ __forceinline__ uint4 f8_to_h8(float4 a, float4 b) {
    __half2 h0 = __floats2half2_rn(a.x, a.y);
    __half2 h1 = __floats2half2_rn(a.z, a.w);
    __half2 h2 = __floats2half2_rn(b.x, b.y);
    __half2 h3 = __floats2half2_rn(b.z, b.w);
    uint4 u;
    u.x = *(uint32_t*)&h0; u.y = *(uint32_t*)&h1;
    u.z = *(uint32_t*)&h2; u.w = *(uint32_t*)&h3;
    return u;
}

#define CP_ASYNC16(dst, src) \
    asm volatile("cp.async.cg.shared.global [%0], [%1], 16;" :: "r"(dst), "l"(src))
#define CP_COMMIT() asm volatile("cp.async.commit_group;")
#define CP_WAIT0()  asm volatile("cp.async.wait_group 0;")
#define CP_WAIT1()  asm volatile("cp.async.wait_group 1;")

// fp16 m16n8k16 fragment lane->address components (offsets in halves):
#define A16_ROW(lane) ((lane) & 15)
#define A16_KOF(lane) (((lane) >> 4) * 8)
#define B16_ROW(lane) (((lane) & 7) + ((lane) >> 4) * 8)
#define B16_KOF(lane) ((((lane) >> 3) & 1) * 8)

// ---------------------------------------------------------------------------
// fp32 -> fp16 conversion (8 elts/thread)
// ---------------------------------------------------------------------------
__global__ __launch_bounds__(256)
void cvt_f32_f16(const float* __restrict__ in, __half* __restrict__ out) {
    int i = (blockIdx.x * 256 + threadIdx.x) * 8;
    float4 a = *(const float4*)(in + i);
    float4 b = *(const float4*)(in + i + 4);
    *(uint4*)(out + i) = f8_to_h8(a, b);
}

// ---------------------------------------------------------------------------
// FP16 GEMM (NT): C[m,n] = sum_k A[m,k]*B[n,k] (+bias[n])
// A,B fp16; C fp32 (BIAS) or fp16. Block 128x256, BK=32, 512 thr = 16 warps
// (4x4), warp tile 32x64. cp.async double-buffered smem, stride 40 halves.
// ---------------------------------------------------------------------------
#define BK 32
#define ASTR 40
#define SA_H (128 * ASTR)
#define SB_H (256 * ASTR)
#define GEMM_SMEM ((2 * (SA_H + SB_H)) * 2)

template <bool BIAS, bool OUT_HALF>
__global__ __launch_bounds__(512, 1)
void f16_gemm_nt(const __half* __restrict__ A, const __half* __restrict__ B,
                 const float* __restrict__ bias, void* __restrict__ Cv,
                 int M, int N, int K) {
    extern __shared__ __half gsm[];

    const int tid  = threadIdx.x;
    const int lane = tid & 31;
    const int warp = tid >> 5;         // 0..15
    const int g = lane >> 2;
    const int t = lane & 3;
    const int wm = (warp >> 2) * 32;
    const int wn = (warp & 3) * 64;
    const int bm = blockIdx.y * 128;
    const int bn = blockIdx.x * 256;

    // staging: thread -> (row = tid>>2, chunk = (tid&3)*8 halves)
    const int srow = tid >> 2;         // 0..127
    const int sch  = (tid & 3) * 8;    // 0,8,16,24

    const __half* Ap  = A + (size_t)(bm + srow) * K + sch;
    const __half* Bp0 = B + (size_t)(bn + srow) * K + sch;
    const __half* Bp1 = B + (size_t)(bn + 128 + srow) * K + sch;

    const uint32_t smem0 = (uint32_t)__cvta_generic_to_shared(gsm);
    const uint32_t sAoff[2] = {smem0, smem0 + 2u * (SA_H + SB_H)};
    const uint32_t sBoff[2] = {smem0 + 2u * SA_H,
                               smem0 + 2u * (2 * SA_H + SB_H)};
    const uint32_t dA  = 2u * (srow * ASTR + sch);
    const uint32_t dB1 = 2u * ((128 + srow) * ASTR + sch);

    const int ar = A16_ROW(lane), ak = A16_KOF(lane);
    const int br = B16_ROW(lane), bk = B16_KOF(lane);

    float acc[2][8][4];
#pragma unroll
    for (int i = 0; i < 2; i++)
#pragma unroll
        for (int j = 0; j < 8; j++)
#pragma unroll
            for (int q = 0; q < 4; q++) acc[i][j][q] = 0.f;

#define G_STAGE(bufi, kt)                                                      \
    do {                                                                       \
        CP_ASYNC16(sAoff[bufi] + dA, Ap + (kt) * BK);                          \
        CP_ASYNC16(sBoff[bufi] + dA, Bp0 + (kt) * BK);                         \
        CP_ASYNC16(sBoff[bufi] + dB1, Bp1 + (kt) * BK);                        \
        CP_COMMIT();                                                           \
    } while (0)

    const int NT = K / BK;
    G_STAGE(0, 0);

    for (int kt = 0; kt < NT; kt++) {
        const int buf = kt & 1;
        if (kt + 1 < NT) {
            G_STAGE(buf ^ 1, kt + 1);
            CP_WAIT1();
        } else {
            CP_WAIT0();
        }
        __syncthreads();

        const uint32_t aA = sAoff[buf];
        const uint32_t aB = sBoff[buf];
#pragma unroll
        for (int kk = 0; kk < 2; kk++) {
            uint32_t af[2][4];
#pragma unroll
            for (int mt = 0; mt < 2; mt++)
                ldsm_x4(af[mt][0], af[mt][1], af[mt][2], af[mt][3],
                        aA + 2u * ((wm + mt * 16 + ar) * ASTR + kk * 16 + ak));
#pragma unroll
            for (int p = 0; p < 4; p++) {
                uint32_t b0, b1, b2, b3;
                ldsm_x4(b0, b1, b2, b3,
                        aB + 2u * ((wn + p * 16 + br) * ASTR + kk * 16 + bk));
#pragma unroll
                for (int mt = 0; mt < 2; mt++) {
                    mma_f16(acc[mt][2 * p],     af[mt], b0, b1);
                    mma_f16(acc[mt][2 * p + 1], af[mt], b2, b3);
                }
            }
        }
        __syncthreads();  // readers done before buf is overwritten next iter
    }

    // Epilogue
#pragma unroll
    for (int mt = 0; mt < 2; mt++) {
#pragma unroll
        for (int nt = 0; nt < 8; nt++) {
            const float* a4 = acc[mt][nt];
            const int row = bm + wm + mt * 16 + g;
            const int col = bn + wn + nt * 8 + 2 * t;
            if (OUT_HALF) {
                __half* C = (__half*)Cv;
                __half2 v0 = __floats2half2_rn(a4[0], a4[1]);
                __half2 v1 = __floats2half2_rn(a4[2], a4[3]);
                *(uint32_t*)&C[(size_t)row * N + col] = *(uint32_t*)&v0;
                *(uint32_t*)&C[(size_t)(row + 8) * N + col] = *(uint32_t*)&v1;
            } else {
                float* C = (float*)Cv;
                float bx = 0.f, by = 0.f;
                if (BIAS) { bx = bias[col]; by = bias[col + 1]; }
                float2 v0 = {a4[0] + bx, a4[1] + by};
                float2 v1 = {a4[2] + bx, a4[3] + by};
                *(float2*)(C + (size_t)row * N + col) = v0;
                *(float2*)(C + (size_t)(row + 8) * N + col) = v1;
            }
        }
    }
}

// ---------------------------------------------------------------------------
// FP16 flash attention, fp16 qkv input, cp.async double-buffered K/V.
// 256 threads = 8 warps, 128 q-rows, 16 kv-tiles of 64.
// smem: kvbuf0{K,V}, kvbuf1{K,V} each [64][72], then sQP [128][72] (Q then P).
// ---------------------------------------------------------------------------
#define FSTR 72
#define KV_H (64 * FSTR)
#define FLASH_HALVES (4 * KV_H + 128 * FSTR)
#define FLASH_SMEM   (FLASH_HALVES * 2)

__global__ __launch_bounds__(256)
void flash_f16(const __half* __restrict__ qkv, __half* __restrict__ att) {
    extern __shared__ __half fsm[];

    const int tid  = threadIdx.x;
    const int lane = tid & 31;
    const int warp = tid >> 5;
    const int g = lane >> 2;
    const int t = lane & 3;
    const int bh = blockIdx.y;
    const int b = bh >> 4;
    const int h = bh & 15;
    const int q0 = blockIdx.x * 128;
    const size_t base = (size_t)b * TSZ * C3;
    const int hoff = h * HDIM;
    const float qscale = 0.125f * 1.44269504088896340736f;  // scale * log2(e)

    const uint32_t smem0 = (uint32_t)__cvta_generic_to_shared(fsm);
    const uint32_t sKb[2] = {smem0, smem0 + 2u * 2 * KV_H};
    const uint32_t sVb[2] = {smem0 + 2u * KV_H, smem0 + 2u * 3 * KV_H};
    const uint32_t sQPb = smem0 + 2u * 4 * KV_H;
    const uint32_t sPwb = sQPb + 2u * (warp * 16 * FSTR);
    __half* sQP = fsm + 4 * KV_H;

    const int ar = A16_ROW(lane), ak = A16_KOF(lane);
    const int br = B16_ROW(lane), bk = B16_KOF(lane);
    const int vj = (lane & 7) + ((lane >> 3) & 1) * 8;
    const int vd = (lane >> 4) * 8;

    // Issue Q staging (group 1): 128 rows x 8 chunks = 1024, 4 per thread
#pragma unroll
    for (int it = 0; it < 4; it++) {
        const int i = tid + it * 256;
        const int r = i >> 3, c8 = (i & 7) * 8;
        CP_ASYNC16(sQPb + 2u * (r * FSTR + c8),
                   qkv + base + (size_t)(q0 + r) * C3 + hoff + c8);
    }
    CP_COMMIT();

    // Issue K/V tile 0 (group 2): 64 rows x 8 chunks x2 = 1024, 4 per thread
#define KV_STAGE(bufi, kt)                                                     \
    do {                                                                       \
        const __half* srcb = qkv + base + (size_t)((kt) * 64) * C3 + hoff;     \
        _Pragma("unroll")                                                      \
        for (int it = 0; it < 2; it++) {                                       \
            const int i = tid + it * 256;                                      \
            const int r = i >> 3, c8 = (i & 7) * 8;                            \
            CP_ASYNC16(sKb[bufi] + 2u * (r * FSTR + c8),                       \
                       srcb + (size_t)r * C3 + DIM + c8);                      \
            CP_ASYNC16(sVb[bufi] + 2u * (r * FSTR + c8),                       \
                       srcb + (size_t)r * C3 + 2 * DIM + c8);                  \
        }                                                                      \
        CP_COMMIT();                                                           \
    } while (0)

    KV_STAGE(0, 0);

    // Wait for Q (<=1 group pending), load Q fragments
    CP_WAIT1();
    __syncthreads();
    uint32_t aq[4][4];
#pragma unroll
    for (int kk = 0; kk < 4; kk++)
        ldsm_x4(aq[kk][0], aq[kk][1], aq[kk][2], aq[kk][3],
                sQPb + 2u * ((warp * 16 + ar) * FSTR + kk * 16 + ak));

    float accO[8][4];
#pragma unroll
    for (int i = 0; i < 8; i++)
#pragma unroll
        for (int j = 0; j < 4; j++) accO[i][j] = 0.f;
    float m0 = -INFINITY, m1 = -INFINITY, l0 = 0.f, l1 = 0.f;

    for (int kt = 0; kt < 16; kt++) {
        const int buf = kt & 1;
        if (kt + 1 < 16) {
            KV_STAGE(buf ^ 1, kt + 1);
            CP_WAIT1();
        } else {
            CP_WAIT0();
        }
        __syncthreads();

        // S = Q * K^T
        float accS[8][4];
#pragma unroll
        for (int i = 0; i < 8; i++)
#pragma unroll
            for (int j = 0; j < 4; j++) accS[i][j] = 0.f;
#pragma unroll
        for (int kk = 0; kk < 4; kk++) {
#pragma unroll
            for (int p = 0; p < 4; p++) {
                uint32_t b0, b1, b2, b3;
                ldsm_x4(b0, b1, b2, b3,
                        sKb[buf] + 2u * ((p * 16 + br) * FSTR + kk * 16 + bk));
                mma_f16(accS[2 * p],     aq[kk], b0, b1);
                mma_f16(accS[2 * p + 1], aq[kk], b2, b3);
            }
        }
#pragma unroll
        for (int nt = 0; nt < 8; nt++) {
            accS[nt][0] *= qscale; accS[nt][1] *= qscale;
            accS[nt][2] *= qscale; accS[nt][3] *= qscale;
        }

        // Online softmax (rows g, g+8), base-2 domain
        float r0 = -INFINITY, r1 = -INFINITY;
#pragma unroll
        for (int nt = 0; nt < 8; nt++) {
            r0 = fmaxf(r0, fmaxf(accS[nt][0], accS[nt][1]));
            r1 = fmaxf(r1, fmaxf(accS[nt][2], accS[nt][3]));
        }
        r0 = fmaxf(r0, __shfl_xor_sync(0xffffffffu, r0, 1));
        r0 = fmaxf(r0, __shfl_xor_sync(0xffffffffu, r0, 2));
        r1 = fmaxf(r1, __shfl_xor_sync(0xffffffffu, r1, 1));
        r1 = fmaxf(r1, __shfl_xor_sync(0xffffffffu, r1, 2));
        const float mn0 = fmaxf(m0, r0);
        const float mn1 = fmaxf(m1, r1);
        const float al0 = exp2f(m0 - mn0);
        const float al1 = exp2f(m1 - mn1);
        float rs0 = 0.f, rs1 = 0.f;
        __half* sPw = sQP + warp * 16 * FSTR;
#pragma unroll
        for (int nt = 0; nt < 8; nt++) {
            __half2 h01 = __floats2half2_rn(exp2f(accS[nt][0] - mn0),
                                            exp2f(accS[nt][1] - mn0));
            __half2 h23 = __floats2half2_rn(exp2f(accS[nt][2] - mn1),
                                            exp2f(accS[nt][3] - mn1));
            float2 f01 = __half22float2(h01);
            float2 f23 = __half22float2(h23);
            rs0 += f01.x + f01.y;
            rs1 += f23.x + f23.y;
            *(uint32_t*)&sPw[g * FSTR + nt * 8 + 2 * t]       = *(uint32_t*)&h01;
            *(uint32_t*)&sPw[(g + 8) * FSTR + nt * 8 + 2 * t] = *(uint32_t*)&h23;
        }
        rs0 += __shfl_xor_sync(0xffffffffu, rs0, 1);
        rs0 += __shfl_xor_sync(0xffffffffu, rs0, 2);
        rs1 += __shfl_xor_sync(0xffffffffu, rs1, 1);
        rs1 += __shfl_xor_sync(0xffffffffu, rs1, 2);
        l0 = l0 * al0 + rs0;
        l1 = l1 * al1 + rs1;
        m0 = mn0; m1 = mn1;
#pragma unroll
        for (int nt = 0; nt < 8; nt++) {
            accO[nt][0] *= al0; accO[nt][1] *= al0;
            accO[nt][2] *= al1; accO[nt][3] *= al1;
        }
        __syncwarp();

        // O += P V (P: A-frag; V: B-frag via ldmatrix.trans)
#pragma unroll
        for (int kk = 0; kk < 4; kk++) {
            uint32_t ap[4];
            ldsm_x4(ap[0], ap[1], ap[2], ap[3],
                    sPwb + 2u * (ar * FSTR + kk * 16 + ak));
#pragma unroll
            for (int p = 0; p < 4; p++) {
                uint32_t v0, v1, v2, v3;
                ldsm_x4_trans(v0, v1, v2, v3,
                              sVb[buf] + 2u * ((kk * 16 + vj) * FSTR + p * 16 + vd));
                mma_f16(accO[2 * p],     ap, v0, v1);
                mma_f16(accO[2 * p + 1], ap, v2, v3);
            }
        }
        __syncthreads();  // readers done before buf overwritten next iter
    }

    // Epilogue: normalize, write fp16 att [B,T,C]
    const float inv0 = 1.f / l0;
    const float inv1 = 1.f / l1;
    const int r0w = q0 + warp * 16 + g;
    __half* o0 = att + (size_t)b * TSZ * DIM + (size_t)r0w * DIM + hoff;
    __half* o1 = o0 + (size_t)8 * DIM;
#pragma unroll
    for (int nt = 0; nt < 8; nt++) {
        __half2 v0 = __floats2half2_rn(accO[nt][0] * inv0, accO[nt][1] * inv0);
        __half2 v1 = __floats2half2_rn(accO[nt][2] * inv1, accO[nt][3] * inv1);
        *(uint32_t*)&o0[nt * 8 + 2 * t] = *(uint32_t*)&v0;
        *(uint32_t*)&o1[nt * 8 + 2 * t] = *(uint32_t*)&v1;
    }
}

// ---------------------------------------------------------------------------
extern "C" void kernel_launch(void* const* d_in, const int* in_sizes, int n_in,
                              void* d_out, int out_size) {
    const float* x     = (const float*)d_in[0];  // [4,1024,1024]
    const float* Wqkv  = (const float*)d_in[1];  // [3072,1024]
    const float* Wproj = (const float*)d_in[2];  // [1024,1024]
    const float* bproj = (const float*)d_in[3];  // [1024]
    float* out = (float*)d_out;                  // [4,1024,1024]

    __half *xh, *wqkvh, *wprojh, *qkvh, *atth;
    cudaGetSymbolAddress((void**)&xh, g_xh);
    cudaGetSymbolAddress((void**)&wqkvh, g_wqkvh);
    cudaGetSymbolAddress((void**)&wprojh, g_wprojh);
    cudaGetSymbolAddress((void**)&qkvh, g_qkvh);
    cudaGetSymbolAddress((void**)&atth, g_atth);

    cudaFuncSetAttribute(f16_gemm_nt<false, true>,
                         cudaFuncAttributeMaxDynamicSharedMemorySize, GEMM_SMEM);
    cudaFuncSetAttribute(f16_gemm_nt<true, false>,
                         cudaFuncAttributeMaxDynamicSharedMemorySize, GEMM_SMEM);
    cudaFuncSetAttribute(flash_f16,
                         cudaFuncAttributeMaxDynamicSharedMemorySize, FLASH_SMEM);

    // 0) fp32 -> fp16 conversions
    cvt_f32_f16<<<(BATCH * TSZ * DIM) / 2048, 256>>>(x, xh);
    cvt_f32_f16<<<(C3 * DIM) / 2048, 256>>>(Wqkv, wqkvh);
    cvt_f32_f16<<<(DIM * DIM) / 2048, 256>>>(Wproj, wprojh);

    // 1) QKV projection -> fp16: [4096,1024] x [3072,1024]^T -> [4096,3072]
    f16_gemm_nt<false, true><<<dim3(C3 / 256, (BATCH * TSZ) / 128), 512,
                               GEMM_SMEM>>>(xh, wqkvh, nullptr, qkvh,
                                            BATCH * TSZ, C3, DIM);

    // 2) Attention (fp16 in/out)
    flash_f16<<<dim3(TSZ / 128, BATCH * NHEAD), 256, FLASH_SMEM>>>(qkvh, atth);

    // 3) Output projection + bias -> fp32 out
    f16_gemm_nt<true, false><<<dim3(DIM / 256, (BATCH * TSZ) / 128), 512,
                               GEMM_SMEM>>>(atth, wprojh, bproj, out,
                                            BATCH * TSZ, DIM, DIM);
}